// round 5
// baseline (speedup 1.0000x reference)
#include <cuda_runtime.h>
#include <stdint.h>

#define BATCH 2
#define NBOX 16384
#define PRE 1024
#define POST 512
#define NMSW 16            // 1024 bits / 64
#define NMS_THRESH 0.8f
#define CAND_CAP 2048
#define SORT_N 2048
#define PAIR_CAP 32768     // per batch
#define NCELLX 13
#define NCELL (NCELLX * NCELLX)
#define HBITS 14
#define HBINS (1 << HBITS)          // 16384 bins of key>>50
#define TPB 1024

typedef unsigned long long u64;

struct __align__(16) Box5 { float x, y, dx, dy, c, s, rad, area; };

__device__ int      g_topidx[BATCH][PRE];
__device__ Box5     g_box[BATCH][PRE];
__device__ float    g_cor[BATCH][PRE][8];
__device__ u64      g_suppby[BATCH][PRE][NMSW]; // supp_by[j]: bits i<j with iou>th
__device__ u64      g_rowflag[BATCH][NMSW];
__device__ int      g_paircount[BATCH];
__device__ unsigned g_pairs[BATCH][PAIR_CAP];   // i<<10 | j
__device__ u64      g_keys[BATCH][NBOX];
__device__ unsigned g_hist[BATCH][HBINS];

__device__ __forceinline__ int cell_of(float v) {
    int c = (int)floorf((v + 50.0f) * 0.125f);
    return c < 0 ? 0 : (c > NCELLX - 1 ? NCELLX - 1 : c);
}

// ==========================================================================
// Z: zero all replay-accumulated state (multi-CTA)
// ==========================================================================
__global__ void zero_kernel() {
    int tid = blockIdx.x * blockDim.x + threadIdx.x;
    int stride = gridDim.x * blockDim.x;
    u64* pm = &g_suppby[0][0][0];
    for (int i = tid; i < BATCH * PRE * NMSW; i += stride) pm[i] = 0ull;
    unsigned* ph = &g_hist[0][0];
    for (int i = tid; i < BATCH * HBINS; i += stride) ph[i] = 0u;
    u64* pf = &g_rowflag[0][0];
    if (tid < BATCH * NMSW) pf[tid] = 0ull;
    if (tid < BATCH) g_paircount[tid] = 0;
}

// ==========================================================================
// A: keys + 14-bit-prefix histogram (multi-CTA, whole chip)
// ==========================================================================
__global__ void key_kernel(const float* __restrict__ cls) {
    int t = blockIdx.x * blockDim.x + threadIdx.x;
    if (t >= BATCH * NBOX) return;
    int b = t >> 14, i = t & (NBOX - 1);
    const float* p = cls + ((long)t) * 3;
    float sc = fmaxf(p[0], fmaxf(p[1], p[2]));
    unsigned u = __float_as_uint(sc);
    unsigned m = (u & 0x80000000u) ? ~u : (u | 0x80000000u); // ascending monotone
    u64 k = (((u64)(~m)) << 32) | (unsigned)i;  // u64 asc == score desc, idx asc
    g_keys[b][i] = k;
    atomicAdd(&g_hist[b][(unsigned)(k >> (64 - HBITS))], 1u);
}

// ==========================================================================
// D: threshold scan + compact + bitonic-2048 + prep + binning + pairgen
//    One CTA per batch (only O(2048) work remains here).
// ==========================================================================
__global__ void select_kernel(const float* __restrict__ boxes) {
    __shared__ u64      cand[SORT_N];       // 16 KB
    __shared__ float4   f4s[PRE];           // 16 KB
    __shared__ int      cellbox[PRE];       // 4 KB
    __shared__ unsigned part[TPB];          // 4 KB
    __shared__ unsigned sc[8];
    __shared__ unsigned ccnt[NCELL];
    __shared__ unsigned cstart[NCELL + 1];

    int b = blockIdx.x;
    int tid = threadIdx.x;

    // ---- threshold scan over 16384-bin histogram ----
    const unsigned* h = g_hist[b];
    unsigned psum = 0;
    {
        const uint4* h4 = (const uint4*)(h + tid * (HBINS / TPB));
#pragma unroll
        for (int k = 0; k < HBINS / TPB / 4; k++) {
            uint4 v = h4[k];
            psum += v.x + v.y + v.z + v.w;
        }
    }
    part[tid] = psum;
    __syncthreads();
    for (int off = 1; off < TPB; off <<= 1) {
        unsigned v = (tid >= off) ? part[tid - off] : 0u;
        __syncthreads();
        part[tid] += v;
        __syncthreads();
    }
    {
        unsigned incl = part[tid];
        unsigned excl = (tid == 0) ? 0u : part[tid - 1];
        if (incl >= PRE && excl < PRE) {
            unsigned c = excl;
            int base = tid * (HBINS / TPB);
            for (int k = 0; k < HBINS / TPB; k++) {
                c += h[base + k];
                if (c >= PRE) { sc[0] = (unsigned)(base + k); break; }
            }
        }
        if (tid == 0) sc[1] = 0;
    }
    __syncthreads();
    unsigned T = sc[0];

    // ---- compact candidates (key prefix <= T) ----
    {
        const u64* keys = g_keys[b];
#pragma unroll
        for (int r = 0; r < NBOX / TPB; r++) {
            u64 k = keys[tid + r * TPB];
            if ((unsigned)(k >> (64 - HBITS)) <= T) {
                unsigned pos = atomicAdd(&sc[1], 1u);
                if (pos < CAND_CAP) cand[pos] = k;
            }
        }
    }
    __syncthreads();
    int m = (int)sc[1]; if (m > CAND_CAP) m = CAND_CAP;
#pragma unroll
    for (int r = 0; r < SORT_N / TPB; r++) {
        int i = tid + r * TPB;
        if (i >= m) cand[i] = ~0ull;
    }
    __syncthreads();

    // ---- bitonic sort of 2048 (asc == score desc, idx asc) ----
    for (unsigned k = 2; k <= SORT_N; k <<= 1) {
        for (unsigned j = k >> 1; j > 0; j >>= 1) {
#pragma unroll
            for (int r = 0; r < SORT_N / TPB; r++) {
                unsigned idx = tid + r * TPB;
                unsigned ixj = idx ^ j;
                if (ixj > idx) {
                    bool up = ((idx & k) == 0);
                    u64 a = cand[idx], c = cand[ixj];
                    if ((a > c) == up) { cand[idx] = c; cand[ixj] = a; }
                }
            }
            __syncthreads();
        }
    }

    // ---- prep + cell binning ----
    if (tid < NCELL) ccnt[tid] = 0u;
    __syncthreads();
    int mycell;
    float4 myf4;
    {
        int idx = (int)(cand[tid] & 0xFFFFFFFFull);
        g_topidx[b][tid] = idx;
        const float* bp = boxes + ((long)b * NBOX + idx) * 7;
        float x = bp[0], y = bp[1], dx = bp[3], dy = bp[4], r = bp[6];
        float c = cosf(r), s = sinf(r);
        Box5 bx;
        bx.x = x; bx.y = y; bx.dx = dx; bx.dy = dy; bx.c = c; bx.s = s;
        bx.rad = 0.5f * sqrtf(dx * dx + dy * dy);
        bx.area = dx * dy;
        g_box[b][tid] = bx;
        myf4 = make_float4(x, y, bx.rad, bx.area);
        f4s[tid] = myf4;
        const float ox[4] = {0.5f, -0.5f, -0.5f, 0.5f};
        const float oy[4] = {0.5f, 0.5f, -0.5f, -0.5f};
        float* co = g_cor[b][tid];
#pragma unroll
        for (int k = 0; k < 4; k++) {
            float lx = dx * ox[k], ly = dy * oy[k];
            co[2 * k]     = x + lx * c - ly * s;
            co[2 * k + 1] = y + lx * s + ly * c;
        }
        mycell = cell_of(y) * NCELLX + cell_of(x);
        atomicAdd(&ccnt[mycell], 1u);
    }
    __syncthreads();
    if (tid == 0) {
        unsigned c = 0;
        for (int x = 0; x < NCELL; x++) { cstart[x] = c; c += ccnt[x]; }
        cstart[NCELL] = c;
    }
    __syncthreads();
    if (tid < NCELL) ccnt[tid] = 0u;
    __syncthreads();
    {
        unsigned pos = cstart[mycell] + atomicAdd(&ccnt[mycell], 1u);
        cellbox[pos] = tid;
    }
    __syncthreads();

    // ---- pair generation (thread i scans its 3x3 neighborhood) ----
    {
        int bcx = cell_of(myf4.x), bcy = cell_of(myf4.y);
#pragma unroll
        for (int n = 0; n < 9; n++) {
            int cx = bcx + (n % 3) - 1;
            int cy = bcy + (n / 3) - 1;
            if (cx < 0 || cx >= NCELLX || cy < 0 || cy >= NCELLX) continue;
            int c = cy * NCELLX + cx;
            int s = cstart[c], e = cstart[c + 1];
            for (int p = s; p < e; p++) {
                int j = cellbox[p];
                if (j <= tid) continue;
                float4 fb = f4s[j];
                float amin = fminf(myf4.w, fb.w), amax = fmaxf(myf4.w, fb.w);
                if (amin < 0.795f * amax) continue;  // iou <= amin/amax < thresh
                float ddx = myf4.x - fb.x, ddy = myf4.y - fb.y;
                float rr = myf4.z + fb.z + 1e-2f;
                if (ddx * ddx + ddy * ddy > rr * rr) continue;
                int pos = atomicAdd(&g_paircount[b], 1);
                if (pos < PAIR_CAP)
                    g_pairs[b][pos] = ((unsigned)tid << 10) | (unsigned)j;
            }
        }
    }
}

// ==========================================================================
// Reference-faithful rotated BEV IoU — fully register-resident.
// Stable odd-even transposition network == reference's stable argsort.
// ==========================================================================
__device__ __forceinline__ float rotated_iou(const Box5& A, const float* __restrict__ CA,
                                             const Box5& Bx, const float* __restrict__ CB) {
    float ptsx[24], ptsy[24];
    int mk[24];
    float axv[4], ayv[4], dax[4], day[4];
    float bxv[4], byv[4], dbx[4], dby[4];
#pragma unroll
    for (int k = 0; k < 4; k++) {
        axv[k] = CA[2 * k]; ayv[k] = CA[2 * k + 1];
        bxv[k] = CB[2 * k]; byv[k] = CB[2 * k + 1];
    }
#pragma unroll
    for (int k = 0; k < 4; k++) {
        int k1 = (k + 1) & 3;
        dax[k] = axv[k1] - axv[k]; day[k] = ayv[k1] - ayv[k];
        dbx[k] = bxv[k1] - bxv[k]; dby[k] = byv[k1] - byv[k];
    }
#pragma unroll
    for (int p = 0; p < 4; p++) {
#pragma unroll
        for (int q = 0; q < 4; q++) {
            int id = p * 4 + q;
            float den = dax[p] * dby[q] - day[p] * dbx[q];
            float ddx = bxv[q] - axv[p];
            float ddy = byv[q] - ayv[p];
            bool denok = fabsf(den) > 1e-8f;
            float dens = denok ? den : 1.0f;
            float t = (ddx * dby[q] - ddy * dbx[q]) / dens;
            float u = (ddx * day[p] - ddy * dax[p]) / dens;
            bool ok = denok && (t >= 0.0f) && (t <= 1.0f) && (u >= 0.0f) && (u <= 1.0f);
            mk[id] = ok ? 1 : 0;
            ptsx[id] = axv[p] + t * dax[p];
            ptsy[id] = ayv[p] + t * day[p];
        }
    }
#pragma unroll
    for (int k = 0; k < 4; k++) {
        float rx = axv[k] - Bx.x, ry = ayv[k] - Bx.y;
        float qx = rx * Bx.c + ry * Bx.s;
        float qy = -rx * Bx.s + ry * Bx.c;
        mk[16 + k] = ((fabsf(qx) <= Bx.dx * 0.5f + 1e-5f) &&
                      (fabsf(qy) <= Bx.dy * 0.5f + 1e-5f)) ? 1 : 0;
        ptsx[16 + k] = axv[k]; ptsy[16 + k] = ayv[k];
    }
#pragma unroll
    for (int k = 0; k < 4; k++) {
        float rx = bxv[k] - A.x, ry = byv[k] - A.y;
        float qx = rx * A.c + ry * A.s;
        float qy = -rx * A.s + ry * A.c;
        mk[20 + k] = ((fabsf(qx) <= A.dx * 0.5f + 1e-5f) &&
                      (fabsf(qy) <= A.dy * 0.5f + 1e-5f)) ? 1 : 0;
        ptsx[20 + k] = bxv[k]; ptsy[20 + k] = byv[k];
    }

    int cnt = 0;
    float sx = 0.0f, sy = 0.0f;
#pragma unroll
    for (int k = 0; k < 24; k++)
        if (mk[k]) { cnt++; sx += ptsx[k]; sy += ptsy[k]; }
    float cf = (float)(cnt > 1 ? cnt : 1);
    float cx = sx / cf, cy = sy / cf;

    float ang[24];
#pragma unroll
    for (int k = 0; k < 24; k++)
        ang[k] = mk[k] ? atan2f(ptsy[k] - cy, ptsx[k] - cx) : 1e9f;

    // stable sort: odd-even transposition, static indices only
#pragma unroll
    for (int rnd = 0; rnd < 24; rnd++) {
        int st = rnd & 1;
#pragma unroll
        for (int k = 0; k < 23; k++) {
            if ((k & 1) == st) {
                if (ang[k] > ang[k + 1]) {
                    float ta = ang[k];  ang[k] = ang[k + 1];  ang[k + 1] = ta;
                    float tx = ptsx[k]; ptsx[k] = ptsx[k + 1]; ptsx[k + 1] = tx;
                    float ty = ptsy[k]; ptsy[k] = ptsy[k + 1]; ptsy[k + 1] = ty;
                    int   tm = mk[k];   mk[k] = mk[k + 1];     mk[k + 1] = tm;
                }
            }
        }
    }

    float fx = ptsx[0], fy = ptsy[0];
    float qxv[24], qyv[24];
#pragma unroll
    for (int k = 0; k < 24; k++) {
        qxv[k] = mk[k] ? ptsx[k] : fx;
        qyv[k] = mk[k] ? ptsy[k] : fy;
    }
    float s2 = 0.0f;
#pragma unroll
    for (int k = 0; k < 24; k++) {
        int k1 = (k + 1) % 24;
        s2 += qxv[k] * qyv[k1] - qyv[k] * qxv[k1];
    }
    float inter = 0.5f * fabsf(s2);
    float un = fmaxf(A.area + Bx.area - inter, 1e-6f);
    return inter / un;
}

// ==========================================================================
// Exact IoU over surviving pairs; writes transposed suppressor masks
// ==========================================================================
__global__ void __launch_bounds__(128) heavy_kernel() {
    int n0 = g_paircount[0]; if (n0 > PAIR_CAP) n0 = PAIR_CAP;
    int n1 = g_paircount[1]; if (n1 > PAIR_CAP) n1 = PAIR_CAP;
    int n = n0 + n1;
    for (int t = blockIdx.x * blockDim.x + threadIdx.x; t < n;
         t += gridDim.x * blockDim.x) {
        int b = (t >= n0) ? 1 : 0;
        unsigned pk = g_pairs[b][b ? (t - n0) : t];
        int i = (pk >> 10) & 1023;
        int j = pk & 1023;
        Box5 A = g_box[b][i];
        Box5 Bx = g_box[b][j];
        float iou = rotated_iou(A, g_cor[b][i], Bx, g_cor[b][j]);
        if (iou > NMS_THRESH) {
            atomicOr(&g_suppby[b][j][i >> 6], 1ull << (i & 63));   // i suppresses j (i<j)
            atomicOr(&g_rowflag[b][j >> 6], 1ull << (j & 63));
        }
    }
}

// ==========================================================================
// Fixpoint greedy NMS + output gather. One 1024-thread block per batch.
// ==========================================================================
__global__ void nms_out_kernel(const float* __restrict__ boxes,
                               const float* __restrict__ cls,
                               float* __restrict__ out, int out_size) {
    __shared__ unsigned kw[32];
    __shared__ int changed;
    int b = blockIdx.x;
    int tid = threadIdx.x;
    int wid = tid >> 5, lane = tid & 31;

    bool flagged = (g_rowflag[b][tid >> 6] >> (tid & 63)) & 1ull;
    u64 sb[NMSW];
#pragma unroll
    for (int w = 0; w < NMSW; w++)
        sb[w] = flagged ? g_suppby[b][tid][w] : 0ull;

    if (tid < 32) kw[tid] = 0xFFFFFFFFu;
    __syncthreads();

    for (int it = 0; it < PRE; it++) {
        u64 sup = 0ull;
        if (flagged) {
#pragma unroll
            for (int w = 0; w < NMSW; w++) {
                u64 Kw = (u64)kw[2 * w] | ((u64)kw[2 * w + 1] << 32);
                sup |= sb[w] & Kw;
            }
        }
        bool kept = (sup == 0ull);
        unsigned bal = __ballot_sync(0xffffffffu, kept);
        __syncthreads();
        if (tid == 0) changed = 0;
        __syncthreads();
        if (lane == 0) {
            if (bal != kw[wid]) { kw[wid] = bal; changed = 1; }
        }
        __syncthreads();
        if (!changed) break;
    }

    int s = tid;
    if (s >= POST) return;
    u64 skeep[NMSW];
#pragma unroll
    for (int w = 0; w < NMSW; w++)
        skeep[w] = (u64)kw[2 * w] | ((u64)kw[2 * w + 1] << 32);

    int pos = -1, c = 0;
#pragma unroll
    for (int w = 0; w < NMSW; w++) {
        u64 kv = skeep[w];
        int pc = __popcll(kv);
        if (pos < 0 && c + pc > s) {
            int r = s - c;
            for (int t = 0; t < r; t++) kv &= kv - 1ull;
            pos = w * 64 + __ffsll((long long)kv) - 1;
        }
        c += pc;
    }
    bool valid = pos >= 0;
    int p = valid ? pos : (PRE - 1);
    int sel = g_topidx[b][p];

    const float* bp = boxes + ((long)b * NBOX + sel) * 7;
    const float* lp = cls + ((long)b * NBOX + sel) * 3;
    float l0 = lp[0], l1 = lp[1], l2 = lp[2];
    float scv = l0; int lab = 0;
    if (l1 > scv) { scv = l1; lab = 1; }
    if (l2 > scv) { scv = l2; lab = 2; }

    const int SC_OFF = BATCH * POST * 7;
    const int LB_OFF = SC_OFF + BATCH * POST;
    const int LG_OFF = LB_OFF + BATCH * POST;
    int base = b * POST + s;

#pragma unroll
    for (int k = 0; k < 7; k++) {
        int o = base * 7 + k;
        if (o < out_size) out[o] = valid ? bp[k] : 0.0f;
    }
    { int o = SC_OFF + base; if (o < out_size) out[o] = valid ? scv : 0.0f; }
    { int o = LB_OFF + base; if (o < out_size) out[o] = valid ? (float)(lab + 1) : 1.0f; }
    {
        float lg[3] = {l0, l1, l2};
#pragma unroll
        for (int k = 0; k < 3; k++) {
            int o = LG_OFF + base * 3 + k;
            if (o < out_size) out[o] = valid ? lg[k] : 0.0f;
        }
    }
}

// ==========================================================================
extern "C" void kernel_launch(void* const* d_in, const int* in_sizes, int n_in,
                              void* d_out, int out_size) {
    const float* boxes = (const float*)d_in[0];  // [2,16384,7]
    const float* cls = (const float*)d_in[1];    // [2,16384,3]
    float* out = (float*)d_out;

    zero_kernel<<<256, 256>>>();
    key_kernel<<<(BATCH * NBOX + 255) / 256, 256>>>(cls);
    select_kernel<<<BATCH, TPB>>>(boxes);
    heavy_kernel<<<64, 128>>>();
    nms_out_kernel<<<BATCH, TPB>>>(boxes, cls, out, out_size);
}

// round 6
// speedup vs baseline: 1.0980x; 1.0980x over previous
#include <cuda_runtime.h>
#include <stdint.h>

#define BATCH 2
#define NBOX 16384
#define PRE 1024
#define POST 512
#define NMSW 16            // 1024 bits / 64
#define NMS_THRESH 0.8f
#define CAND_CAP 2048
#define SORT_N 2048
#define PAIR_CAP 32768     // per batch
#define NCELLX 13
#define NCELL (NCELLX * NCELLX)
#define HBITS 14
#define HBINS (1 << HBITS)
#define TPB 1024

typedef unsigned long long u64;

struct __align__(16) Box5 { float x, y, dx, dy, c, s, rad, area; };

__device__ int      g_topidx[BATCH][PRE];
__device__ Box5     g_box[BATCH][PRE];
__device__ float    g_cor[BATCH][PRE][8];
__device__ u64      g_suppby[BATCH][PRE][NMSW]; // supp_by[j]: bits i<j with iou>th
__device__ u64      g_rowflag[BATCH][NMSW];
__device__ int      g_paircount[BATCH];
__device__ unsigned g_pairs[BATCH][PAIR_CAP];   // i<<10 | j
__device__ u64      g_keys[BATCH][NBOX];
__device__ unsigned g_hist[BATCH][HBINS];

__device__ __forceinline__ int cell_of(float v) {
    int c = (int)floorf((v + 50.0f) * 0.125f);
    return c < 0 ? 0 : (c > NCELLX - 1 ? NCELLX - 1 : c);
}

// ==========================================================================
// Z: zero all replay-accumulated state (multi-CTA)
// ==========================================================================
__global__ void zero_kernel() {
    int tid = blockIdx.x * blockDim.x + threadIdx.x;
    int stride = gridDim.x * blockDim.x;
    u64* pm = &g_suppby[0][0][0];
    for (int i = tid; i < BATCH * PRE * NMSW; i += stride) pm[i] = 0ull;
    unsigned* ph = &g_hist[0][0];
    for (int i = tid; i < BATCH * HBINS; i += stride) ph[i] = 0u;
    u64* pf = &g_rowflag[0][0];
    if (tid < BATCH * NMSW) pf[tid] = 0ull;
    if (tid < BATCH) g_paircount[tid] = 0;
}

// ==========================================================================
// A: keys + 14-bit-prefix histogram (multi-CTA)
// ==========================================================================
__global__ void key_kernel(const float* __restrict__ cls) {
    int t = blockIdx.x * blockDim.x + threadIdx.x;
    if (t >= BATCH * NBOX) return;
    int b = t >> 14, i = t & (NBOX - 1);
    const float* p = cls + ((long)t) * 3;
    float sc = fmaxf(p[0], fmaxf(p[1], p[2]));
    unsigned u = __float_as_uint(sc);
    unsigned m = (u & 0x80000000u) ? ~u : (u | 0x80000000u); // ascending monotone
    u64 k = (((u64)(~m)) << 32) | (unsigned)i;  // u64 asc == score desc, idx asc
    g_keys[b][i] = k;
    atomicAdd(&g_hist[b][(unsigned)(k >> (64 - HBITS))], 1u);
}

// ==========================================================================
// D: threshold scan + compact + bitonic-2048 + prep + binning + pairgen
// ==========================================================================
__global__ void select_kernel(const float* __restrict__ boxes) {
    __shared__ u64      cand[SORT_N];
    __shared__ float4   f4s[PRE];
    __shared__ int      cellbox[PRE];
    __shared__ unsigned part[TPB];
    __shared__ unsigned sc[8];
    __shared__ unsigned ccnt[NCELL];
    __shared__ unsigned cstart[NCELL + 1];

    int b = blockIdx.x;
    int tid = threadIdx.x;

    // ---- threshold scan over 16384-bin histogram ----
    const unsigned* h = g_hist[b];
    unsigned psum = 0;
    {
        const uint4* h4 = (const uint4*)(h + tid * (HBINS / TPB));
#pragma unroll
        for (int k = 0; k < HBINS / TPB / 4; k++) {
            uint4 v = h4[k];
            psum += v.x + v.y + v.z + v.w;
        }
    }
    part[tid] = psum;
    __syncthreads();
    for (int off = 1; off < TPB; off <<= 1) {
        unsigned v = (tid >= off) ? part[tid - off] : 0u;
        __syncthreads();
        part[tid] += v;
        __syncthreads();
    }
    {
        unsigned incl = part[tid];
        unsigned excl = (tid == 0) ? 0u : part[tid - 1];
        if (incl >= PRE && excl < PRE) {
            unsigned c = excl;
            int base = tid * (HBINS / TPB);
            for (int k = 0; k < HBINS / TPB; k++) {
                c += h[base + k];
                if (c >= PRE) { sc[0] = (unsigned)(base + k); break; }
            }
        }
        if (tid == 0) sc[1] = 0;
    }
    __syncthreads();
    unsigned T = sc[0];

    // ---- compact candidates ----
    {
        const u64* keys = g_keys[b];
#pragma unroll
        for (int r = 0; r < NBOX / TPB; r++) {
            u64 k = keys[tid + r * TPB];
            if ((unsigned)(k >> (64 - HBITS)) <= T) {
                unsigned pos = atomicAdd(&sc[1], 1u);
                if (pos < CAND_CAP) cand[pos] = k;
            }
        }
    }
    __syncthreads();
    int m = (int)sc[1]; if (m > CAND_CAP) m = CAND_CAP;
#pragma unroll
    for (int r = 0; r < SORT_N / TPB; r++) {
        int i = tid + r * TPB;
        if (i >= m) cand[i] = ~0ull;
    }
    __syncthreads();

    // ---- bitonic sort of 2048 ----
    for (unsigned k = 2; k <= SORT_N; k <<= 1) {
        for (unsigned j = k >> 1; j > 0; j >>= 1) {
#pragma unroll
            for (int r = 0; r < SORT_N / TPB; r++) {
                unsigned idx = tid + r * TPB;
                unsigned ixj = idx ^ j;
                if (ixj > idx) {
                    bool up = ((idx & k) == 0);
                    u64 a = cand[idx], c = cand[ixj];
                    if ((a > c) == up) { cand[idx] = c; cand[ixj] = a; }
                }
            }
            __syncthreads();
        }
    }

    // ---- prep + cell binning ----
    if (tid < NCELL) ccnt[tid] = 0u;
    __syncthreads();
    int mycell;
    float4 myf4;
    {
        int idx = (int)(cand[tid] & 0xFFFFFFFFull);
        g_topidx[b][tid] = idx;
        const float* bp = boxes + ((long)b * NBOX + idx) * 7;
        float x = bp[0], y = bp[1], dx = bp[3], dy = bp[4], r = bp[6];
        float c = cosf(r), s = sinf(r);
        Box5 bx;
        bx.x = x; bx.y = y; bx.dx = dx; bx.dy = dy; bx.c = c; bx.s = s;
        bx.rad = 0.5f * sqrtf(dx * dx + dy * dy);
        bx.area = dx * dy;
        g_box[b][tid] = bx;
        myf4 = make_float4(x, y, bx.rad, bx.area);
        f4s[tid] = myf4;
        const float ox[4] = {0.5f, -0.5f, -0.5f, 0.5f};
        const float oy[4] = {0.5f, 0.5f, -0.5f, -0.5f};
        float* co = g_cor[b][tid];
#pragma unroll
        for (int k = 0; k < 4; k++) {
            float lx = dx * ox[k], ly = dy * oy[k];
            co[2 * k]     = x + lx * c - ly * s;
            co[2 * k + 1] = y + lx * s + ly * c;
        }
        mycell = cell_of(y) * NCELLX + cell_of(x);
        atomicAdd(&ccnt[mycell], 1u);
    }
    __syncthreads();
    if (tid == 0) {
        unsigned c = 0;
        for (int x = 0; x < NCELL; x++) { cstart[x] = c; c += ccnt[x]; }
        cstart[NCELL] = c;
    }
    __syncthreads();
    if (tid < NCELL) ccnt[tid] = 0u;
    __syncthreads();
    {
        unsigned pos = cstart[mycell] + atomicAdd(&ccnt[mycell], 1u);
        cellbox[pos] = tid;
    }
    __syncthreads();

    // ---- pair generation ----
    {
        int bcx = cell_of(myf4.x), bcy = cell_of(myf4.y);
#pragma unroll
        for (int n = 0; n < 9; n++) {
            int cx = bcx + (n % 3) - 1;
            int cy = bcy + (n / 3) - 1;
            if (cx < 0 || cx >= NCELLX || cy < 0 || cy >= NCELLX) continue;
            int c = cy * NCELLX + cx;
            int s = cstart[c], e = cstart[c + 1];
            for (int p = s; p < e; p++) {
                int j = cellbox[p];
                if (j <= tid) continue;
                float4 fb = f4s[j];
                float amin = fminf(myf4.w, fb.w), amax = fmaxf(myf4.w, fb.w);
                if (amin < 0.795f * amax) continue;  // iou <= amin/amax < thresh
                float ddx = myf4.x - fb.x, ddy = myf4.y - fb.y;
                float rr = myf4.z + fb.z + 1e-2f;
                if (ddx * ddx + ddy * ddy > rr * rr) continue;
                int pos = atomicAdd(&g_paircount[b], 1);
                if (pos < PAIR_CAP)
                    g_pairs[b][pos] = ((unsigned)tid << 10) | (unsigned)j;
            }
        }
    }
}

// ==========================================================================
// Warp-parallel reference-faithful rotated BEV IoU.
// Lane k owns point k (16 edge-edge, 4 A-in-B, 4 B-in-A, 8 pad).
// Sequential-order sums via shfl gather; stable sort via unique u64 keys.
// ==========================================================================
__device__ __forceinline__ float warp_rotated_iou(int b, int i, int j, int lane) {
    const unsigned FULL = 0xffffffffu;
    Box5 A  = g_box[b][i];
    Box5 Bx = g_box[b][j];
    const float* CA = g_cor[b][i];
    const float* CB = g_cor[b][j];

    float px = 0.0f, py = 0.0f;
    bool ok = false;
    if (lane < 16) {
        int p = lane >> 2, q = lane & 3;
        int p1 = (p + 1) & 3, q1 = (q + 1) & 3;
        float ax = CA[2 * p],  ay = CA[2 * p + 1];
        float dax = CA[2 * p1] - ax, day = CA[2 * p1 + 1] - ay;
        float bx = CB[2 * q],  by = CB[2 * q + 1];
        float dbx = CB[2 * q1] - bx, dby = CB[2 * q1 + 1] - by;
        float den = dax * dby - day * dbx;
        float ddx = bx - ax, ddy = by - ay;
        bool denok = fabsf(den) > 1e-8f;
        float dens = denok ? den : 1.0f;
        float t = (ddx * dby - ddy * dbx) / dens;
        float u = (ddx * day - ddy * dax) / dens;
        ok = denok && (t >= 0.0f) && (t <= 1.0f) && (u >= 0.0f) && (u <= 1.0f);
        px = ax + t * dax;
        py = ay + t * day;
    } else if (lane < 20) {
        int k = lane - 16;
        px = CA[2 * k]; py = CA[2 * k + 1];
        float rx = px - Bx.x, ry = py - Bx.y;
        float qx = rx * Bx.c + ry * Bx.s;
        float qy = -rx * Bx.s + ry * Bx.c;
        ok = (fabsf(qx) <= Bx.dx * 0.5f + 1e-5f) &&
             (fabsf(qy) <= Bx.dy * 0.5f + 1e-5f);
    } else if (lane < 24) {
        int k = lane - 20;
        px = CB[2 * k]; py = CB[2 * k + 1];
        float rx = px - A.x, ry = py - A.y;
        float qx = rx * A.c + ry * A.s;
        float qy = -rx * A.s + ry * A.c;
        ok = (fabsf(qx) <= A.dx * 0.5f + 1e-5f) &&
             (fabsf(qy) <= A.dy * 0.5f + 1e-5f);
    }
    unsigned mbits = __ballot_sync(FULL, ok) & 0xFFFFFFu;
    int cnt = __popc(mbits);

    // masked centroid: strict sequential order 0..23 (bit-exact vs reference path)
    float sx = 0.0f, sy = 0.0f;
#pragma unroll
    for (int k = 0; k < 24; k++) {
        float vx = __shfl_sync(FULL, px, k);
        float vy = __shfl_sync(FULL, py, k);
        if ((mbits >> k) & 1u) { sx += vx; sy += vy; }
    }
    float cf = (float)(cnt > 1 ? cnt : 1);
    float cx = sx / cf, cy = sy / cf;

    // angle per lane; masked -> 1e9
    float ang = ((lane < 24) && ok) ? atan2f(py - cy, px - cx) : 1e9f;

    // sort key: (monotonic(ang) << 32) | lane  -- unique, stable tie-break by lane
    u64 key;
    if (lane < 24) {
        unsigned u = __float_as_uint(ang);
        unsigned m = (u & 0x80000000u) ? ~u : (u | 0x80000000u);
        key = (((u64)m) << 32) | (unsigned)lane;
    } else {
        key = (((u64)0xFFFFFFFFu) << 32) | (unsigned)lane;  // pads sort last
    }

    // 32-wide bitonic sort via shfl_xor
#pragma unroll
    for (unsigned k = 2; k <= 32; k <<= 1) {
#pragma unroll
        for (unsigned jj = k >> 1; jj > 0; jj >>= 1) {
            u64 partner = __shfl_xor_sync(FULL, key, jj);
            bool dirAsc = ((lane & k) == 0);
            bool keepMin = (((lane & jj) == 0) == dirAsc);
            bool take = keepMin ? (partner < key) : (partner > key);
            if (k == 32) { // final merge: ascending everywhere
                take = (((lane & jj) == 0)) ? (partner < key) : (partner > key);
            }
            if (take) key = partner;
        }
    }
    // lane r now holds r-th smallest key; sorted position r -> original idx
    int sidx = (int)(key & 31u);

    // pts_s[r]: gather original point via dynamic shfl
    float psx = __shfl_sync(FULL, px, sidx);
    float psy = __shfl_sync(FULL, py, sidx);
    bool msk_s = (sidx < 24) && ((mbits >> sidx) & 1u);

    // first = pts_s[0]
    float fx = __shfl_sync(FULL, psx, 0);
    float fy = __shfl_sync(FULL, psy, 0);
    float polx = msk_s ? psx : fx;
    float poly = msk_s ? psy : fy;

    // shoelace: strict sequential order k=0..23, cyclic
    float s2 = 0.0f;
    float curx = __shfl_sync(FULL, polx, 0);
    float cury = __shfl_sync(FULL, poly, 0);
    float firstx = curx, firsty = cury;
#pragma unroll
    for (int k = 0; k < 24; k++) {
        float nxx, nxy;
        if (k == 23) { nxx = firstx; nxy = firsty; }
        else {
            nxx = __shfl_sync(FULL, polx, k + 1);
            nxy = __shfl_sync(FULL, poly, k + 1);
        }
        s2 += curx * nxy - cury * nxx;
        curx = nxx; cury = nxy;
    }
    float inter = 0.5f * fabsf(s2);
    float un = fmaxf(A.area + Bx.area - inter, 1e-6f);
    return inter / un;
}

// ==========================================================================
// One warp per pair
// ==========================================================================
__global__ void __launch_bounds__(256) heavy_kernel() {
    int n0 = g_paircount[0]; if (n0 > PAIR_CAP) n0 = PAIR_CAP;
    int n1 = g_paircount[1]; if (n1 > PAIR_CAP) n1 = PAIR_CAP;
    int n = n0 + n1;
    int lane = threadIdx.x & 31;
    int w = (blockIdx.x * blockDim.x + threadIdx.x) >> 5;
    int nw = (gridDim.x * blockDim.x) >> 5;
    for (int t = w; t < n; t += nw) {
        int b = (t >= n0) ? 1 : 0;
        unsigned pk = g_pairs[b][b ? (t - n0) : t];
        int i = (pk >> 10) & 1023;
        int j = pk & 1023;
        float iou = warp_rotated_iou(b, i, j, lane);
        if (lane == 0 && iou > NMS_THRESH) {
            atomicOr(&g_suppby[b][j][i >> 6], 1ull << (i & 63));   // i suppresses j (i<j)
            atomicOr(&g_rowflag[b][j >> 6], 1ull << (j & 63));
        }
    }
}

// ==========================================================================
// Fixpoint greedy NMS + output gather. One 1024-thread block per batch.
// ==========================================================================
__global__ void nms_out_kernel(const float* __restrict__ boxes,
                               const float* __restrict__ cls,
                               float* __restrict__ out, int out_size) {
    __shared__ unsigned kw[32];
    __shared__ int changed;
    int b = blockIdx.x;
    int tid = threadIdx.x;
    int wid = tid >> 5, lane = tid & 31;

    bool flagged = (g_rowflag[b][tid >> 6] >> (tid & 63)) & 1ull;
    u64 sb[NMSW];
#pragma unroll
    for (int w = 0; w < NMSW; w++)
        sb[w] = flagged ? g_suppby[b][tid][w] : 0ull;

    if (tid < 32) kw[tid] = 0xFFFFFFFFu;
    __syncthreads();

    for (int it = 0; it < PRE; it++) {
        u64 sup = 0ull;
        if (flagged) {
#pragma unroll
            for (int w = 0; w < NMSW; w++) {
                u64 Kw = (u64)kw[2 * w] | ((u64)kw[2 * w + 1] << 32);
                sup |= sb[w] & Kw;
            }
        }
        bool kept = (sup == 0ull);
        unsigned bal = __ballot_sync(0xffffffffu, kept);
        __syncthreads();
        if (tid == 0) changed = 0;
        __syncthreads();
        if (lane == 0) {
            if (bal != kw[wid]) { kw[wid] = bal; changed = 1; }
        }
        __syncthreads();
        if (!changed) break;
    }

    int s = tid;
    if (s >= POST) return;
    u64 skeep[NMSW];
#pragma unroll
    for (int w = 0; w < NMSW; w++)
        skeep[w] = (u64)kw[2 * w] | ((u64)kw[2 * w + 1] << 32);

    int pos = -1, c = 0;
#pragma unroll
    for (int w = 0; w < NMSW; w++) {
        u64 kv = skeep[w];
        int pc = __popcll(kv);
        if (pos < 0 && c + pc > s) {
            int r = s - c;
            for (int t = 0; t < r; t++) kv &= kv - 1ull;
            pos = w * 64 + __ffsll((long long)kv) - 1;
        }
        c += pc;
    }
    bool valid = pos >= 0;
    int p = valid ? pos : (PRE - 1);
    int sel = g_topidx[b][p];

    const float* bp = boxes + ((long)b * NBOX + sel) * 7;
    const float* lp = cls + ((long)b * NBOX + sel) * 3;
    float l0 = lp[0], l1 = lp[1], l2 = lp[2];
    float scv = l0; int lab = 0;
    if (l1 > scv) { scv = l1; lab = 1; }
    if (l2 > scv) { scv = l2; lab = 2; }

    const int SC_OFF = BATCH * POST * 7;
    const int LB_OFF = SC_OFF + BATCH * POST;
    const int LG_OFF = LB_OFF + BATCH * POST;
    int base = b * POST + s;

#pragma unroll
    for (int k = 0; k < 7; k++) {
        int o = base * 7 + k;
        if (o < out_size) out[o] = valid ? bp[k] : 0.0f;
    }
    { int o = SC_OFF + base; if (o < out_size) out[o] = valid ? scv : 0.0f; }
    { int o = LB_OFF + base; if (o < out_size) out[o] = valid ? (float)(lab + 1) : 1.0f; }
    {
        float lg[3] = {l0, l1, l2};
#pragma unroll
        for (int k = 0; k < 3; k++) {
            int o = LG_OFF + base * 3 + k;
            if (o < out_size) out[o] = valid ? lg[k] : 0.0f;
        }
    }
}

// ==========================================================================
extern "C" void kernel_launch(void* const* d_in, const int* in_sizes, int n_in,
                              void* d_out, int out_size) {
    const float* boxes = (const float*)d_in[0];  // [2,16384,7]
    const float* cls = (const float*)d_in[1];    // [2,16384,3]
    float* out = (float*)d_out;

    zero_kernel<<<256, 256>>>();
    key_kernel<<<(BATCH * NBOX + 255) / 256, 256>>>(cls);
    select_kernel<<<BATCH, TPB>>>(boxes);
    heavy_kernel<<<128, 256>>>();
    nms_out_kernel<<<BATCH, TPB>>>(boxes, cls, out, out_size);
}

// round 7
// speedup vs baseline: 1.1444x; 1.0423x over previous
#include <cuda_runtime.h>
#include <stdint.h>

#define BATCH 2
#define NBOX 16384
#define PRE 1024
#define POST 512
#define NMSW 16            // 1024 bits / 64
#define NMS_THRESH 0.8f
#define CAND_CAP 2048
#define SORT_N 2048
#define PAIR_CAP 32768     // per batch
#define NCELLX 13
#define NCELL (NCELLX * NCELLX)
#define HBITS 14
#define HBINS (1 << HBITS)
#define TPB 1024

typedef unsigned long long u64;

struct __align__(16) Box5 { float x, y, dx, dy, c, s, rad, area; };

__device__ int      g_topidx[BATCH][PRE];
__device__ Box5     g_box[BATCH][PRE];
__device__ float    g_cor[BATCH][PRE][8];
__device__ u64      g_suppby[BATCH][PRE][NMSW]; // supp_by[j]: bits i<j with iou>th
__device__ u64      g_rowflag[BATCH][NMSW];
__device__ int      g_paircount[BATCH];
__device__ unsigned g_pairs[BATCH][PAIR_CAP];   // i<<10 | j
__device__ u64      g_keys[BATCH][NBOX];
__device__ unsigned g_hist[BATCH][HBINS];
__device__ unsigned g_thresh[BATCH];
__device__ int      g_ccount[BATCH];
__device__ u64      g_cand[BATCH][CAND_CAP];

__device__ __forceinline__ int cell_of(float v) {
    int c = (int)floorf((v + 50.0f) * 0.125f);
    return c < 0 ? 0 : (c > NCELLX - 1 ? NCELLX - 1 : c);
}

// ==========================================================================
// Z: zero all replay-accumulated state (multi-CTA)
// ==========================================================================
__global__ void zero_kernel() {
    int tid = blockIdx.x * blockDim.x + threadIdx.x;
    int stride = gridDim.x * blockDim.x;
    u64* pm = &g_suppby[0][0][0];
    for (int i = tid; i < BATCH * PRE * NMSW; i += stride) pm[i] = 0ull;
    unsigned* ph = &g_hist[0][0];
    for (int i = tid; i < BATCH * HBINS; i += stride) ph[i] = 0u;
    u64* pf = &g_rowflag[0][0];
    if (tid < BATCH * NMSW) pf[tid] = 0ull;
    if (tid < BATCH) { g_paircount[tid] = 0; g_ccount[tid] = 0; }
}

// ==========================================================================
// A: keys + 14-bit-prefix histogram (multi-CTA)
// ==========================================================================
__global__ void key_kernel(const float* __restrict__ cls) {
    int t = blockIdx.x * blockDim.x + threadIdx.x;
    if (t >= BATCH * NBOX) return;
    int b = t >> 14, i = t & (NBOX - 1);
    const float* p = cls + ((long)t) * 3;
    float sc = fmaxf(p[0], fmaxf(p[1], p[2]));
    unsigned u = __float_as_uint(sc);
    unsigned m = (u & 0x80000000u) ? ~u : (u | 0x80000000u); // ascending monotone
    u64 k = (((u64)(~m)) << 32) | (unsigned)i;  // u64 asc == score desc, idx asc
    g_keys[b][i] = k;
    atomicAdd(&g_hist[b][(unsigned)(k >> (64 - HBITS))], 1u);
}

// ==========================================================================
// B: threshold bin (smallest T with cum count >= PRE). One CTA per batch.
// ==========================================================================
__global__ void thresh_kernel() {
    __shared__ unsigned part[TPB];
    int b = blockIdx.x, tid = threadIdx.x;
    const unsigned* h = g_hist[b];
    unsigned psum = 0;
    {
        const uint4* h4 = (const uint4*)(h + tid * (HBINS / TPB));
#pragma unroll
        for (int k = 0; k < HBINS / TPB / 4; k++) {
            uint4 v = h4[k];
            psum += v.x + v.y + v.z + v.w;
        }
    }
    part[tid] = psum;
    __syncthreads();
    for (int off = 1; off < TPB; off <<= 1) {
        unsigned v = (tid >= off) ? part[tid - off] : 0u;
        __syncthreads();
        part[tid] += v;
        __syncthreads();
    }
    unsigned incl = part[tid];
    unsigned excl = (tid == 0) ? 0u : part[tid - 1];
    if (incl >= PRE && excl < PRE) {
        unsigned c = excl;
        int base = tid * (HBINS / TPB);
        for (int k = 0; k < HBINS / TPB; k++) {
            c += h[base + k];
            if (c >= PRE) { g_thresh[b] = (unsigned)(base + k); break; }
        }
    }
}

// ==========================================================================
// C: multi-CTA compaction of candidates (key prefix <= threshold)
// ==========================================================================
__global__ void compact_kernel() {
    int t = blockIdx.x * blockDim.x + threadIdx.x;
    if (t >= BATCH * NBOX) return;
    int b = t >> 14, i = t & (NBOX - 1);
    u64 k = g_keys[b][i];
    if ((unsigned)(k >> (64 - HBITS)) <= g_thresh[b]) {
        int pos = atomicAdd(&g_ccount[b], 1);
        if (pos < CAND_CAP) g_cand[b][pos] = k;
    }
}

// ==========================================================================
// D: bitonic-2048 sort + prep + binning + pairgen (O(2048) only, 1 CTA/batch)
// ==========================================================================
__global__ void sort_kernel(const float* __restrict__ boxes) {
    __shared__ u64      cand[SORT_N];       // 16 KB
    __shared__ float4   f4s[PRE];           // 16 KB
    __shared__ int      cellbox[PRE];       // 4 KB
    __shared__ unsigned ccnt[NCELL];
    __shared__ unsigned cstart[NCELL + 1];

    int b = blockIdx.x;
    int tid = threadIdx.x;

    int m = g_ccount[b]; if (m > CAND_CAP) m = CAND_CAP;
#pragma unroll
    for (int r = 0; r < SORT_N / TPB; r++) {
        int i = tid + r * TPB;
        cand[i] = (i < m) ? g_cand[b][i] : ~0ull;
    }
    __syncthreads();

    // ---- bitonic sort of 2048 (asc == score desc, idx asc) ----
    for (unsigned k = 2; k <= SORT_N; k <<= 1) {
        for (unsigned j = k >> 1; j > 0; j >>= 1) {
#pragma unroll
            for (int r = 0; r < SORT_N / TPB; r++) {
                unsigned idx = tid + r * TPB;
                unsigned ixj = idx ^ j;
                if (ixj > idx) {
                    bool up = ((idx & k) == 0);
                    u64 a = cand[idx], c = cand[ixj];
                    if ((a > c) == up) { cand[idx] = c; cand[ixj] = a; }
                }
            }
            __syncthreads();
        }
    }

    // ---- prep + cell binning ----
    if (tid < NCELL) ccnt[tid] = 0u;
    __syncthreads();
    int mycell;
    float4 myf4;
    {
        int idx = (int)(cand[tid] & 0xFFFFFFFFull);
        g_topidx[b][tid] = idx;
        const float* bp = boxes + ((long)b * NBOX + idx) * 7;
        float x = bp[0], y = bp[1], dx = bp[3], dy = bp[4], r = bp[6];
        float c = cosf(r), s = sinf(r);
        Box5 bx;
        bx.x = x; bx.y = y; bx.dx = dx; bx.dy = dy; bx.c = c; bx.s = s;
        bx.rad = 0.5f * sqrtf(dx * dx + dy * dy);
        bx.area = dx * dy;
        g_box[b][tid] = bx;
        myf4 = make_float4(x, y, bx.rad, bx.area);
        f4s[tid] = myf4;
        const float ox[4] = {0.5f, -0.5f, -0.5f, 0.5f};
        const float oy[4] = {0.5f, 0.5f, -0.5f, -0.5f};
        float* co = g_cor[b][tid];
#pragma unroll
        for (int k = 0; k < 4; k++) {
            float lx = dx * ox[k], ly = dy * oy[k];
            co[2 * k]     = x + lx * c - ly * s;
            co[2 * k + 1] = y + lx * s + ly * c;
        }
        mycell = cell_of(y) * NCELLX + cell_of(x);
        atomicAdd(&ccnt[mycell], 1u);
    }
    __syncthreads();
    if (tid == 0) {
        unsigned c = 0;
        for (int x = 0; x < NCELL; x++) { cstart[x] = c; c += ccnt[x]; }
        cstart[NCELL] = c;
    }
    __syncthreads();
    if (tid < NCELL) ccnt[tid] = 0u;
    __syncthreads();
    {
        unsigned pos = cstart[mycell] + atomicAdd(&ccnt[mycell], 1u);
        cellbox[pos] = tid;
    }
    __syncthreads();

    // ---- pair generation ----
    {
        int bcx = cell_of(myf4.x), bcy = cell_of(myf4.y);
#pragma unroll
        for (int n = 0; n < 9; n++) {
            int cx = bcx + (n % 3) - 1;
            int cy = bcy + (n / 3) - 1;
            if (cx < 0 || cx >= NCELLX || cy < 0 || cy >= NCELLX) continue;
            int c = cy * NCELLX + cx;
            int s = cstart[c], e = cstart[c + 1];
            for (int p = s; p < e; p++) {
                int j = cellbox[p];
                if (j <= tid) continue;
                float4 fb = f4s[j];
                float amin = fminf(myf4.w, fb.w), amax = fmaxf(myf4.w, fb.w);
                if (amin < 0.795f * amax) continue;  // iou <= amin/amax < thresh
                float ddx = myf4.x - fb.x, ddy = myf4.y - fb.y;
                float rr = myf4.z + fb.z + 1e-2f;
                if (ddx * ddx + ddy * ddy > rr * rr) continue;
                int pos = atomicAdd(&g_paircount[b], 1);
                if (pos < PAIR_CAP)
                    g_pairs[b][pos] = ((unsigned)tid << 10) | (unsigned)j;
            }
        }
    }
}

// ==========================================================================
// Warp-parallel reference-faithful rotated BEV IoU (unchanged from R6)
// ==========================================================================
__device__ __forceinline__ float warp_rotated_iou(int b, int i, int j, int lane) {
    const unsigned FULL = 0xffffffffu;
    Box5 A  = g_box[b][i];
    Box5 Bx = g_box[b][j];
    const float* CA = g_cor[b][i];
    const float* CB = g_cor[b][j];

    float px = 0.0f, py = 0.0f;
    bool ok = false;
    if (lane < 16) {
        int p = lane >> 2, q = lane & 3;
        int p1 = (p + 1) & 3, q1 = (q + 1) & 3;
        float ax = CA[2 * p],  ay = CA[2 * p + 1];
        float dax = CA[2 * p1] - ax, day = CA[2 * p1 + 1] - ay;
        float bx = CB[2 * q],  by = CB[2 * q + 1];
        float dbx = CB[2 * q1] - bx, dby = CB[2 * q1 + 1] - by;
        float den = dax * dby - day * dbx;
        float ddx = bx - ax, ddy = by - ay;
        bool denok = fabsf(den) > 1e-8f;
        float dens = denok ? den : 1.0f;
        float t = (ddx * dby - ddy * dbx) / dens;
        float u = (ddx * day - ddy * dax) / dens;
        ok = denok && (t >= 0.0f) && (t <= 1.0f) && (u >= 0.0f) && (u <= 1.0f);
        px = ax + t * dax;
        py = ay + t * day;
    } else if (lane < 20) {
        int k = lane - 16;
        px = CA[2 * k]; py = CA[2 * k + 1];
        float rx = px - Bx.x, ry = py - Bx.y;
        float qx = rx * Bx.c + ry * Bx.s;
        float qy = -rx * Bx.s + ry * Bx.c;
        ok = (fabsf(qx) <= Bx.dx * 0.5f + 1e-5f) &&
             (fabsf(qy) <= Bx.dy * 0.5f + 1e-5f);
    } else if (lane < 24) {
        int k = lane - 20;
        px = CB[2 * k]; py = CB[2 * k + 1];
        float rx = px - A.x, ry = py - A.y;
        float qx = rx * A.c + ry * A.s;
        float qy = -rx * A.s + ry * A.c;
        ok = (fabsf(qx) <= A.dx * 0.5f + 1e-5f) &&
             (fabsf(qy) <= A.dy * 0.5f + 1e-5f);
    }
    unsigned mbits = __ballot_sync(FULL, ok) & 0xFFFFFFu;
    int cnt = __popc(mbits);

    // masked centroid: strict sequential order 0..23
    float sx = 0.0f, sy = 0.0f;
#pragma unroll
    for (int k = 0; k < 24; k++) {
        float vx = __shfl_sync(FULL, px, k);
        float vy = __shfl_sync(FULL, py, k);
        if ((mbits >> k) & 1u) { sx += vx; sy += vy; }
    }
    float cf = (float)(cnt > 1 ? cnt : 1);
    float cx = sx / cf, cy = sy / cf;

    float ang = ((lane < 24) && ok) ? atan2f(py - cy, px - cx) : 1e9f;

    u64 key;
    if (lane < 24) {
        unsigned u = __float_as_uint(ang);
        unsigned m = (u & 0x80000000u) ? ~u : (u | 0x80000000u);
        key = (((u64)m) << 32) | (unsigned)lane;
    } else {
        key = (((u64)0xFFFFFFFFu) << 32) | (unsigned)lane;
    }

#pragma unroll
    for (unsigned k = 2; k <= 32; k <<= 1) {
#pragma unroll
        for (unsigned jj = k >> 1; jj > 0; jj >>= 1) {
            u64 partner = __shfl_xor_sync(FULL, key, jj);
            bool dirAsc = ((lane & k) == 0);
            bool keepMin = (((lane & jj) == 0) == dirAsc);
            bool take = keepMin ? (partner < key) : (partner > key);
            if (k == 32) {
                take = (((lane & jj) == 0)) ? (partner < key) : (partner > key);
            }
            if (take) key = partner;
        }
    }
    int sidx = (int)(key & 31u);

    float psx = __shfl_sync(FULL, px, sidx);
    float psy = __shfl_sync(FULL, py, sidx);
    bool msk_s = (sidx < 24) && ((mbits >> sidx) & 1u);

    float fx = __shfl_sync(FULL, psx, 0);
    float fy = __shfl_sync(FULL, psy, 0);
    float polx = msk_s ? psx : fx;
    float poly = msk_s ? psy : fy;

    float s2 = 0.0f;
    float curx = __shfl_sync(FULL, polx, 0);
    float cury = __shfl_sync(FULL, poly, 0);
    float firstx = curx, firsty = cury;
#pragma unroll
    for (int k = 0; k < 24; k++) {
        float nxx, nxy;
        if (k == 23) { nxx = firstx; nxy = firsty; }
        else {
            nxx = __shfl_sync(FULL, polx, k + 1);
            nxy = __shfl_sync(FULL, poly, k + 1);
        }
        s2 += curx * nxy - cury * nxx;
        curx = nxx; cury = nxy;
    }
    float inter = 0.5f * fabsf(s2);
    float un = fmaxf(A.area + Bx.area - inter, 1e-6f);
    return inter / un;
}

// ==========================================================================
// One warp per pair
// ==========================================================================
__global__ void __launch_bounds__(256) heavy_kernel() {
    int n0 = g_paircount[0]; if (n0 > PAIR_CAP) n0 = PAIR_CAP;
    int n1 = g_paircount[1]; if (n1 > PAIR_CAP) n1 = PAIR_CAP;
    int n = n0 + n1;
    int lane = threadIdx.x & 31;
    int w = (blockIdx.x * blockDim.x + threadIdx.x) >> 5;
    int nw = (gridDim.x * blockDim.x) >> 5;
    for (int t = w; t < n; t += nw) {
        int b = (t >= n0) ? 1 : 0;
        unsigned pk = g_pairs[b][b ? (t - n0) : t];
        int i = (pk >> 10) & 1023;
        int j = pk & 1023;
        float iou = warp_rotated_iou(b, i, j, lane);
        if (lane == 0 && iou > NMS_THRESH) {
            atomicOr(&g_suppby[b][j][i >> 6], 1ull << (i & 63));
            atomicOr(&g_rowflag[b][j >> 6], 1ull << (j & 63));
        }
    }
}

// ==========================================================================
// Fixpoint greedy NMS + output gather. One 1024-thread block per batch.
// ==========================================================================
__global__ void nms_out_kernel(const float* __restrict__ boxes,
                               const float* __restrict__ cls,
                               float* __restrict__ out, int out_size) {
    __shared__ unsigned kw[32];
    __shared__ int changed;
    int b = blockIdx.x;
    int tid = threadIdx.x;
    int wid = tid >> 5, lane = tid & 31;

    bool flagged = (g_rowflag[b][tid >> 6] >> (tid & 63)) & 1ull;
    u64 sb[NMSW];
#pragma unroll
    for (int w = 0; w < NMSW; w++)
        sb[w] = flagged ? g_suppby[b][tid][w] : 0ull;

    if (tid < 32) kw[tid] = 0xFFFFFFFFu;
    __syncthreads();

    for (int it = 0; it < PRE; it++) {
        u64 sup = 0ull;
        if (flagged) {
#pragma unroll
            for (int w = 0; w < NMSW; w++) {
                u64 Kw = (u64)kw[2 * w] | ((u64)kw[2 * w + 1] << 32);
                sup |= sb[w] & Kw;
            }
        }
        bool kept = (sup == 0ull);
        unsigned bal = __ballot_sync(0xffffffffu, kept);
        __syncthreads();
        if (tid == 0) changed = 0;
        __syncthreads();
        if (lane == 0) {
            if (bal != kw[wid]) { kw[wid] = bal; changed = 1; }
        }
        __syncthreads();
        if (!changed) break;
    }

    int s = tid;
    if (s >= POST) return;
    u64 skeep[NMSW];
#pragma unroll
    for (int w = 0; w < NMSW; w++)
        skeep[w] = (u64)kw[2 * w] | ((u64)kw[2 * w + 1] << 32);

    int pos = -1, c = 0;
#pragma unroll
    for (int w = 0; w < NMSW; w++) {
        u64 kv = skeep[w];
        int pc = __popcll(kv);
        if (pos < 0 && c + pc > s) {
            int r = s - c;
            for (int t = 0; t < r; t++) kv &= kv - 1ull;
            pos = w * 64 + __ffsll((long long)kv) - 1;
        }
        c += pc;
    }
    bool valid = pos >= 0;
    int p = valid ? pos : (PRE - 1);
    int sel = g_topidx[b][p];

    const float* bp = boxes + ((long)b * NBOX + sel) * 7;
    const float* lp = cls + ((long)b * NBOX + sel) * 3;
    float l0 = lp[0], l1 = lp[1], l2 = lp[2];
    float scv = l0; int lab = 0;
    if (l1 > scv) { scv = l1; lab = 1; }
    if (l2 > scv) { scv = l2; lab = 2; }

    const int SC_OFF = BATCH * POST * 7;
    const int LB_OFF = SC_OFF + BATCH * POST;
    const int LG_OFF = LB_OFF + BATCH * POST;
    int base = b * POST + s;

#pragma unroll
    for (int k = 0; k < 7; k++) {
        int o = base * 7 + k;
        if (o < out_size) out[o] = valid ? bp[k] : 0.0f;
    }
    { int o = SC_OFF + base; if (o < out_size) out[o] = valid ? scv : 0.0f; }
    { int o = LB_OFF + base; if (o < out_size) out[o] = valid ? (float)(lab + 1) : 1.0f; }
    {
        float lg[3] = {l0, l1, l2};
#pragma unroll
        for (int k = 0; k < 3; k++) {
            int o = LG_OFF + base * 3 + k;
            if (o < out_size) out[o] = valid ? lg[k] : 0.0f;
        }
    }
}

// ==========================================================================
extern "C" void kernel_launch(void* const* d_in, const int* in_sizes, int n_in,
                              void* d_out, int out_size) {
    const float* boxes = (const float*)d_in[0];  // [2,16384,7]
    const float* cls = (const float*)d_in[1];    // [2,16384,3]
    float* out = (float*)d_out;

    zero_kernel<<<256, 256>>>();
    key_kernel<<<(BATCH * NBOX + 255) / 256, 256>>>(cls);
    thresh_kernel<<<BATCH, TPB>>>();
    compact_kernel<<<(BATCH * NBOX + 255) / 256, 256>>>();
    sort_kernel<<<BATCH, TPB>>>(boxes);
    heavy_kernel<<<128, 256>>>();
    nms_out_kernel<<<BATCH, TPB>>>(boxes, cls, out, out_size);
}